// round 7
// baseline (speedup 1.0000x reference)
#include <cuda_runtime.h>
#include <cuda_bf16.h>
#include <cstdint>

#define N_NODES  100000
#define N_EDGES  1600000
#define IN_CH    128
#define HID      256
#define OUT_CH   128
#define N_GRAPHS 2048

// ---------------- scratch (device globals: no allocation allowed) ----------------
__device__ int   g_deg[N_NODES];
__device__ int   g_fill[N_NODES];
__device__ int   g_rowptr[N_NODES + 1];
__device__ int   g_col[N_EDGES];
__device__ int   g_part[128];
__device__ int   g_part2[128];
__device__ int   g_gcnt[N_GRAPHS];
__device__ uint16_t g_Ah[(size_t)N_NODES * 512];
__device__ uint16_t g_Al[(size_t)N_NODES * 512];
__device__ uint16_t g_B1h[256 * 512], g_B1l[256 * 512];
__device__ uint16_t g_B2h[256 * 512], g_B2l[256 * 512];
__device__ float g_h1 [(size_t)N_NODES * HID];
__device__ float g_pool  [N_GRAPHS * HID];
__device__ float g_hidden[N_GRAPHS * HID];

// ---------------- helpers ----------------
__device__ __forceinline__ uint16_t bf_hi_bits(float v, float& hf) {
    __nv_bfloat16 b = __float2bfloat16_rn(v);
    hf = __bfloat162float(b);
    return *(uint16_t*)&b;
}
__device__ __forceinline__ uint16_t bf_bits(float v) {
    __nv_bfloat16 b = __float2bfloat16_rn(v);
    return *(uint16_t*)&b;
}
__device__ __forceinline__ uint32_t smem_u32(const void* p) {
    uint32_t a;
    asm("{ .reg .u64 t; cvta.to.shared.u64 t, %1; cvt.u32.u64 %0, t; }" : "=r"(a) : "l"(p));
    return a;
}
__device__ __forceinline__ void cp16(uint32_t saddr, const void* gaddr, int szz) {
    asm volatile("cp.async.cg.shared.global [%0], [%1], 16, %2;"
                 :: "r"(saddr), "l"(gaddr), "r"(szz) : "memory");
}
__device__ __forceinline__ void cp_commit() {
    asm volatile("cp.async.commit_group;" ::: "memory");
}
template <int N>
__device__ __forceinline__ void cp_wait() {
    asm volatile("cp.async.wait_group %0;" :: "n"(N) : "memory");
}

// packed f32x2 helpers (head MLP GEMM)
__device__ __forceinline__ void fma2(unsigned long long& c, unsigned long long a, unsigned long long b) {
    asm("fma.rn.f32x2 %0, %1, %2, %3;" : "=l"(c) : "l"(a), "l"(b), "l"(c));
}
__device__ __forceinline__ unsigned long long pk2(float lo, float hi) {
    unsigned long long r; asm("mov.b64 %0, {%1, %2};" : "=l"(r) : "f"(lo), "f"(hi)); return r;
}
__device__ __forceinline__ unsigned long long dup2(float x) {
    unsigned long long r; asm("mov.b64 %0, {%1, %1};" : "=l"(r) : "f"(x)); return r;
}
__device__ __forceinline__ float2 upk2(unsigned long long v) {
    float2 r; asm("mov.b64 {%0, %1}, %2;" : "=f"(r.x), "=f"(r.y) : "l"(v)); return r;
}

// ---------------- CSR build + zero ----------------
__global__ void zero_kernel() {
    int i = blockIdx.x * blockDim.x + threadIdx.x;
    if (i < N_NODES) { g_deg[i] = 0; g_fill[i] = 0; }
    if (i < N_GRAPHS * HID) g_pool[i] = 0.f;
    if (i < N_GRAPHS) g_gcnt[i] = 0;
}
__global__ void hist_kernel(const int* __restrict__ dst, const int* __restrict__ batch) {
    int e = blockIdx.x * blockDim.x + threadIdx.x;
    if (e < N_EDGES) atomicAdd(&g_deg[dst[e]], 1);
    if (e < N_NODES) atomicAdd(&g_gcnt[batch[e]], 1);
}
__global__ void scan1_kernel() {
    __shared__ int sh[1024];
    int t = threadIdx.x;
    int i = blockIdx.x * 1024 + t;
    sh[t] = (i < N_NODES) ? g_deg[i] : 0;
    __syncthreads();
    for (int off = 512; off > 0; off >>= 1) {
        if (t < off) sh[t] += sh[t + off];
        __syncthreads();
    }
    if (t == 0) g_part[blockIdx.x] = sh[0];
}
__global__ void scan2_kernel(int nparts) {
    __shared__ int sh[128];
    int t = threadIdx.x;
    int v = (t < nparts) ? g_part[t] : 0;
    sh[t] = v;
    __syncthreads();
    for (int off = 1; off < 128; off <<= 1) {
        int nv = (t >= off) ? sh[t - off] : 0;
        __syncthreads();
        sh[t] += nv;
        __syncthreads();
    }
    if (t < nparts) g_part2[t] = sh[t] - v;
    if (t == 0) g_rowptr[N_NODES] = N_EDGES;
}
__global__ void scan3_kernel() {
    __shared__ int sh[1024];
    int t = threadIdx.x;
    int i = blockIdx.x * 1024 + t;
    int v = (i < N_NODES) ? g_deg[i] : 0;
    sh[t] = v;
    __syncthreads();
    for (int off = 1; off < 1024; off <<= 1) {
        int nv = (t >= off) ? sh[t - off] : 0;
        __syncthreads();
        sh[t] += nv;
        __syncthreads();
    }
    if (i < N_NODES) g_rowptr[i] = sh[t] - v + g_part2[blockIdx.x];
}
__global__ void scatter_kernel(const int* __restrict__ src, const int* __restrict__ dst) {
    int e = blockIdx.x * blockDim.x + threadIdx.x;
    if (e >= N_EDGES) return;
    int d = dst[e];
    int p = g_rowptr[d] + atomicAdd(&g_fill[d], 1);
    g_col[p] = src[e];
}

// ---------------- split writers ----------------
__device__ __forceinline__ void split_store4(uint16_t* Ah, uint16_t* Al, size_t base,
                                             float v0, float v1, float v2, float v3) {
    float hf0, hf1, hf2, hf3;
    uint16_t h0 = bf_hi_bits(v0, hf0), h1 = bf_hi_bits(v1, hf1);
    uint16_t h2 = bf_hi_bits(v2, hf2), h3 = bf_hi_bits(v3, hf3);
    uint16_t l0 = bf_bits(v0 - hf0), l1 = bf_bits(v1 - hf1);
    uint16_t l2 = bf_bits(v2 - hf2), l3 = bf_bits(v3 - hf3);
    *(uint2*)(Ah + base) = make_uint2((uint32_t)h0 | ((uint32_t)h1 << 16),
                                      (uint32_t)h2 | ((uint32_t)h3 << 16));
    *(uint2*)(Al + base) = make_uint2((uint32_t)l0 | ((uint32_t)l1 << 16),
                                      (uint32_t)l2 | ((uint32_t)l3 << 16));
}

// mean aggregation (one warp per node, 2-way edge unroll) with fused split
template <int C>
__global__ void agg_split_kernel(const float* __restrict__ feat,
                                 uint16_t* __restrict__ Ah, uint16_t* __restrict__ Al) {
    int w = (blockIdx.x * blockDim.x + threadIdx.x) >> 5;
    int lane = threadIdx.x & 31;
    if (w >= N_NODES) return;
    int beg = g_rowptr[w], end = g_rowptr[w + 1];
    constexpr int V = C / 128;
    float4 acc[V];
#pragma unroll
    for (int v = 0; v < V; v++) acc[v] = make_float4(0.f, 0.f, 0.f, 0.f);
    int j = beg;
    for (; j + 1 < end; j += 2) {
        int s0 = g_col[j], s1 = g_col[j + 1];
        const float4* r0 = (const float4*)(feat + (size_t)s0 * C);
        const float4* r1 = (const float4*)(feat + (size_t)s1 * C);
#pragma unroll
        for (int v = 0; v < V; v++) {
            float4 t0 = r0[lane + 32 * v];
            float4 t1 = r1[lane + 32 * v];
            acc[v].x += t0.x; acc[v].y += t0.y; acc[v].z += t0.z; acc[v].w += t0.w;
            acc[v].x += t1.x; acc[v].y += t1.y; acc[v].z += t1.z; acc[v].w += t1.w;
        }
    }
    if (j < end) {
        int s0 = g_col[j];
        const float4* r0 = (const float4*)(feat + (size_t)s0 * C);
#pragma unroll
        for (int v = 0; v < V; v++) {
            float4 t0 = r0[lane + 32 * v];
            acc[v].x += t0.x; acc[v].y += t0.y; acc[v].z += t0.z; acc[v].w += t0.w;
        }
    }
    float inv = (end > beg) ? 1.f / (float)(end - beg) : 0.f;
#pragma unroll
    for (int v = 0; v < V; v++) {
        size_t base = (size_t)w * 512 + (size_t)(lane + 32 * v) * 4;
        split_store4(Ah, Al, base, acc[v].x * inv, acc[v].y * inv, acc[v].z * inv, acc[v].w * inv);
    }
}

// split x (fp32 [N,128]) into A panel cols 128..255
__global__ void xsplit_kernel(const float* __restrict__ x,
                              uint16_t* __restrict__ Ah, uint16_t* __restrict__ Al) {
    int idx = blockIdx.x * blockDim.x + threadIdx.x;
    if (idx >= N_NODES * 32) return;
    int row = idx >> 5, q = idx & 31;
    float4 v = ((const float4*)x)[idx];
    split_store4(Ah, Al, (size_t)row * 512 + 128 + (size_t)q * 4, v.x, v.y, v.z, v.w);
}

// transpose + split weight W[Kw,256] into B panel
__global__ void wsplit_kernel(const float* __restrict__ W, int Kw, int cofs,
                              uint16_t* __restrict__ Bh, uint16_t* __restrict__ Bl) {
    int idx = blockIdx.x * blockDim.x + threadIdx.x;
    if (idx >= 256 * Kw) return;
    int n = idx / Kw, k = idx - n * Kw;
    float v = W[(size_t)k * 256 + n];
    float hf; uint16_t h = bf_hi_bits(v, hf);
    Bh[(size_t)n * 512 + cofs + k] = h;
    Bl[(size_t)n * 512 + cofs + k] = bf_bits(v - hf);
}

// ---------------- pre-split bf16 HMMA GEMM, cp.async double-buffered ----------------
#define LDB_S 40
#define STAGE_BYTES 40960

__device__ __forceinline__ void mma_bf16(float* c, const uint32_t* a, const uint32_t* b) {
    asm volatile(
        "mma.sync.aligned.m16n8k16.row.col.f32.bf16.bf16.f32 "
        "{%0,%1,%2,%3}, {%4,%5,%6,%7}, {%8,%9}, {%0,%1,%2,%3};"
        : "+f"(c[0]), "+f"(c[1]), "+f"(c[2]), "+f"(c[3])
        : "r"(a[0]), "r"(a[1]), "r"(a[2]), "r"(a[3]), "r"(b[0]), "r"(b[1]));
}
__device__ __forceinline__ void ldsm_x4(uint32_t* r, uint32_t addr) {
    asm volatile("ldmatrix.sync.aligned.m8n8.x4.shared.b16 {%0,%1,%2,%3}, [%4];"
                 : "=r"(r[0]), "=r"(r[1]), "=r"(r[2]), "=r"(r[3]) : "r"(addr));
}

__global__ __launch_bounds__(256, 1) void hgemm_kernel(
    const uint16_t* __restrict__ Ah, const uint16_t* __restrict__ Al,
    const uint16_t* __restrict__ Bh, const uint16_t* __restrict__ Bl,
    int K, const float* __restrict__ bias, float* __restrict__ Cc,
    uint16_t* __restrict__ oAh, uint16_t* __restrict__ oAl,
    int M, const int* __restrict__ batchp, float* __restrict__ psum, int fuse_pool)
{
    extern __shared__ __align__(16) uint8_t sm[];

    const int tid = threadIdx.x;
    const int lane = tid & 31, wid = tid >> 5;
    const int wm = wid & 3, wn = wid >> 2;
    const int g = lane >> 2, th = lane & 3;
    const int row0 = blockIdx.x * 128;
    const int n0 = blockIdx.y * 128;

    const uint32_t sbase = smem_u32(sm);
    const int nch = K >> 5;

    float acc[2][8][4];
#pragma unroll
    for (int mt = 0; mt < 2; mt++)
#pragma unroll
        for (int nt = 0; nt < 8; nt++)
#pragma unroll
            for (int r = 0; r < 4; r++) acc[mt][nt][r] = 0.f;

    const int lt = lane >> 3, lr = lane & 7;
    // loader mapping: 2 16B-units per thread per array; u = tid*2+i, row=u>>2, q=u&3
    // issue loads for chunk c into stage s
    auto issue_stage = [&](int c, int s) {
        uint32_t st = sbase + s * STAGE_BYTES;
        int kb = c * 32;
#pragma unroll
        for (int i = 0; i < 2; i++) {
            int u = tid * 2 + i;
            int r = u >> 2, q = u & 3;
            int so = r * 80 + q * 16;
            int ga = row0 + r;
            size_t ao = (size_t)ga * 512 + kb + q * 8;
            int sz = (ga < M) ? 16 : 0;
            cp16(st + so,         Ah + ao, sz);
            cp16(st + 10240 + so, Al + ao, sz);
            size_t bo = (size_t)(n0 + r) * 512 + kb + q * 8;
            cp16(st + 20480 + so, Bh + bo, 16);
            cp16(st + 30720 + so, Bl + bo, 16);
        }
        cp_commit();
    };

    issue_stage(0, 0);

#pragma unroll 1
    for (int c = 0; c < nch; c++) {
        int s = c & 1;
        if (c + 1 < nch) {
            issue_stage(c + 1, s ^ 1);
            cp_wait<1>();
        } else {
            cp_wait<0>();
        }
        __syncthreads();

        const uint32_t sAh = sbase + s * STAGE_BYTES;
        const uint32_t sAl = sAh + 10240;
        const uint32_t sBh = sAh + 20480;
        const uint32_t sBl = sAh + 30720;

#pragma unroll
        for (int step = 0; step < 2; step++) {
            const int k0 = step * 16;
            uint32_t aoff[2];
#pragma unroll
            for (int mt = 0; mt < 2; mt++) {
                int ar = wm * 32 + mt * 16 + (lt & 1) * 8 + lr;
                int ak = k0 + (lt >> 1) * 8;
                aoff[mt] = (uint32_t)(ar * LDB_S + ak) * 2;
            }
            uint32_t boff[4];
#pragma unroll
            for (int ntp = 0; ntp < 4; ntp++) {
                int nr = wn * 64 + ntp * 16 + (lt >> 1) * 8 + lr;
                int nk = k0 + (lt & 1) * 8;
                boff[ntp] = (uint32_t)(nr * LDB_S + nk) * 2;
            }

            uint32_t ah[2][4], al[2][4], bh[4][4], bl[4][4];
#pragma unroll
            for (int mt = 0; mt < 2; mt++) ldsm_x4(ah[mt], sAh + aoff[mt]);
#pragma unroll
            for (int ntp = 0; ntp < 4; ntp++) ldsm_x4(bh[ntp], sBh + boff[ntp]);
#pragma unroll
            for (int mt = 0; mt < 2; mt++)
#pragma unroll
                for (int nt = 0; nt < 8; nt++)
                    mma_bf16(acc[mt][nt], ah[mt], &bh[nt >> 1][(nt & 1) * 2]);

#pragma unroll
            for (int mt = 0; mt < 2; mt++) ldsm_x4(al[mt], sAl + aoff[mt]);
#pragma unroll
            for (int mt = 0; mt < 2; mt++)
#pragma unroll
                for (int nt = 0; nt < 8; nt++)
                    mma_bf16(acc[mt][nt], al[mt], &bh[nt >> 1][(nt & 1) * 2]);

#pragma unroll
            for (int ntp = 0; ntp < 4; ntp++) ldsm_x4(bl[ntp], sBl + boff[ntp]);
#pragma unroll
            for (int mt = 0; mt < 2; mt++)
#pragma unroll
                for (int nt = 0; nt < 8; nt++)
                    mma_bf16(acc[mt][nt], ah[mt], &bl[nt >> 1][(nt & 1) * 2]);
        }
        __syncthreads();
    }

    if (!fuse_pool) {
#pragma unroll
        for (int mt = 0; mt < 2; mt++) {
            int rbase = row0 + wm * 32 + mt * 16 + g;
#pragma unroll
            for (int nt = 0; nt < 8; nt++) {
                int col = n0 + wn * 64 + nt * 8 + th * 2;
                float bx = bias[col], by = bias[col + 1];
                float2 v0 = make_float2(fmaxf(acc[mt][nt][0] + bx, 0.f),
                                        fmaxf(acc[mt][nt][1] + by, 0.f));
                float2 v1 = make_float2(fmaxf(acc[mt][nt][2] + bx, 0.f),
                                        fmaxf(acc[mt][nt][3] + by, 0.f));
                if (rbase < M) {
                    *(float2*)(Cc + (size_t)rbase * 256 + col) = v0;
                    float hf0, hf1;
                    uint16_t h0 = bf_hi_bits(v0.x, hf0), h1 = bf_hi_bits(v0.y, hf1);
                    uint16_t l0 = bf_bits(v0.x - hf0),   l1 = bf_bits(v0.y - hf1);
                    size_t ob = (size_t)rbase * 512 + 256 + col;
                    *(uint32_t*)(oAh + ob) = (uint32_t)h0 | ((uint32_t)h1 << 16);
                    *(uint32_t*)(oAl + ob) = (uint32_t)l0 | ((uint32_t)l1 << 16);
                }
                if (rbase + 8 < M) {
                    *(float2*)(Cc + (size_t)(rbase + 8) * 256 + col) = v1;
                    float hf0, hf1;
                    uint16_t h0 = bf_hi_bits(v1.x, hf0), h1 = bf_hi_bits(v1.y, hf1);
                    uint16_t l0 = bf_bits(v1.x - hf0),   l1 = bf_bits(v1.y - hf1);
                    size_t ob = (size_t)(rbase + 8) * 512 + 256 + col;
                    *(uint32_t*)(oAh + ob) = (uint32_t)h0 | ((uint32_t)h1 << 16);
                    *(uint32_t*)(oAl + ob) = (uint32_t)l0 | ((uint32_t)l1 << 16);
                }
            }
        }
    } else {
        float* red = (float*)sm;                 // [128][66]
        int*   sbat = (int*)(sm + 33792);        // [128]
#pragma unroll 1
        for (int h = 0; h < 2; h++) {
            __syncthreads();
            if (tid < 128) sbat[tid] = (row0 + tid < M) ? batchp[row0 + tid] : -1;
            if (wn == h) {
#pragma unroll
                for (int mt = 0; mt < 2; mt++) {
                    int rl = wm * 32 + mt * 16 + g;
#pragma unroll
                    for (int nt = 0; nt < 8; nt++) {
                        int cl = nt * 8 + th * 2;
                        int colg = n0 + h * 64 + cl;
                        float bx = bias[colg], by = bias[colg + 1];
                        red[rl * 66 + cl]       = fmaxf(acc[mt][nt][0] + bx, 0.f);
                        red[rl * 66 + cl + 1]   = fmaxf(acc[mt][nt][1] + by, 0.f);
                        red[(rl + 8) * 66 + cl]     = fmaxf(acc[mt][nt][2] + bx, 0.f);
                        red[(rl + 8) * 66 + cl + 1] = fmaxf(acc[mt][nt][3] + by, 0.f);
                    }
                }
            }
            __syncthreads();
            int cl = tid & 63, rh = tid >> 6;
            float run = 0.f; int cur = -1;
#pragma unroll 1
            for (int r = rh * 32; r < rh * 32 + 32; r++) {
                int gb = sbat[r];
                if (gb != cur) {
                    if (cur >= 0)
                        atomicAdd(&psum[(size_t)cur * 256 + n0 + h * 64 + cl], run);
                    run = 0.f; cur = gb;
                }
                if (gb >= 0) run += red[r * 66 + cl];
            }
            if (cur >= 0)
                atomicAdd(&psum[(size_t)cur * 256 + n0 + h * 64 + cl], run);
        }
    }
}

// ---------------- finalize pooled means ----------------
__global__ void finalize_kernel() {
    int i = blockIdx.x * blockDim.x + threadIdx.x;
    if (i >= N_GRAPHS * HID) return;
    float c = (float)g_gcnt[i >> 8];
    g_pool[i] = g_pool[i] / fmaxf(c, 1.f);
}

// ---------------- fp32 GEMM (head MLP only; small) ----------------
__global__ __launch_bounds__(256, 2) void gemm_bias_act(
    const float* __restrict__ A1, int K1, const float* __restrict__ B1,
    const float* __restrict__ bias, float* __restrict__ Cc,
    int M, int Nout, int do_relu)
{
    __shared__ float As[8][132];
    __shared__ float Bs[8][128];
    int tid = threadIdx.x;
    int tx = tid & 15, ty = tid >> 4;
    int row0 = blockIdx.x * 128;
    int col0 = blockIdx.y * 128;

    unsigned long long acc[8][4];
#pragma unroll
    for (int i = 0; i < 8; i++)
#pragma unroll
        for (int j = 0; j < 4; j++) acc[i][j] = 0ull;

    int lm = tid >> 1, lk = (tid & 1) * 4;
    int bk = tid >> 5, bn = (tid & 31) * 4;

#pragma unroll 1
    for (int k0 = 0; k0 < K1; k0 += 8) {
        float4 av = make_float4(0.f, 0.f, 0.f, 0.f);
        int r = row0 + lm;
        if (r < M) av = *(const float4*)(A1 + (size_t)r * K1 + k0 + lk);
        float4 bv = *(const float4*)(B1 + (size_t)(k0 + bk) * Nout + col0 + bn);
        __syncthreads();
        As[lk + 0][lm] = av.x; As[lk + 1][lm] = av.y;
        As[lk + 2][lm] = av.z; As[lk + 3][lm] = av.w;
        *(float4*)&Bs[bk][bn] = bv;
        __syncthreads();
#pragma unroll
        for (int k = 0; k < 8; k++) {
            float4 a0 = *(const float4*)&As[k][ty * 4];
            float4 a1 = *(const float4*)&As[k][64 + ty * 4];
            float4 b0 = *(const float4*)&Bs[k][tx * 4];
            float4 b1 = *(const float4*)&Bs[k][64 + tx * 4];
            unsigned long long bp[4];
            bp[0] = pk2(b0.x, b0.y); bp[1] = pk2(b0.z, b0.w);
            bp[2] = pk2(b1.x, b1.y); bp[3] = pk2(b1.z, b1.w);
            float a[8] = {a0.x, a0.y, a0.z, a0.w, a1.x, a1.y, a1.z, a1.w};
#pragma unroll
            for (int i = 0; i < 8; i++) {
                unsigned long long ai = dup2(a[i]);
                fma2(acc[i][0], ai, bp[0]);
                fma2(acc[i][1], ai, bp[1]);
                fma2(acc[i][2], ai, bp[2]);
                fma2(acc[i][3], ai, bp[3]);
            }
        }
    }
#pragma unroll
    for (int i = 0; i < 8; i++) {
        int r = row0 + ((i < 4) ? ty * 4 + i : 64 + ty * 4 + (i - 4));
        if (r >= M) continue;
#pragma unroll
        for (int j = 0; j < 4; j++) {
            int c = col0 + ((j < 2) ? tx * 4 + j * 2 : 64 + tx * 4 + (j - 2) * 2);
            float2 v = upk2(acc[i][j]);
            v.x += bias[c]; v.y += bias[c + 1];
            if (do_relu) { v.x = fmaxf(v.x, 0.f); v.y = fmaxf(v.y, 0.f); }
            *(float2*)(Cc + (size_t)r * Nout + c) = v;
        }
    }
}

// ---------------- launch ----------------
extern "C" void kernel_launch(void* const* d_in, const int* in_sizes, int n_in,
                              void* d_out, int out_size) {
    const float* x   = (const float*)d_in[0];
    const int*   ei  = (const int*)d_in[1];
    const int*   src = ei;
    const int*   dst = ei + N_EDGES;
    const int* batch = (const int*)d_in[2];
    const float* W1l = (const float*)d_in[3];
    const float* b1  = (const float*)d_in[4];
    const float* W1r = (const float*)d_in[5];
    const float* W2l = (const float*)d_in[6];
    const float* b2  = (const float*)d_in[7];
    const float* W2r = (const float*)d_in[8];
    const float* W3  = (const float*)d_in[9];
    const float* b3  = (const float*)d_in[10];
    const float* W4  = (const float*)d_in[11];
    const float* b4  = (const float*)d_in[12];
    float* out = (float*)d_out;

    void *p_h1, *p_pool, *p_hidden, *p_Ah, *p_Al, *p_B1h, *p_B1l, *p_B2h, *p_B2l;
    cudaGetSymbolAddress(&p_h1, g_h1);
    cudaGetSymbolAddress(&p_pool, g_pool);
    cudaGetSymbolAddress(&p_hidden, g_hidden);
    cudaGetSymbolAddress(&p_Ah, g_Ah);
    cudaGetSymbolAddress(&p_Al, g_Al);
    cudaGetSymbolAddress(&p_B1h, g_B1h);
    cudaGetSymbolAddress(&p_B1l, g_B1l);
    cudaGetSymbolAddress(&p_B2h, g_B2h);
    cudaGetSymbolAddress(&p_B2l, g_B2l);
    float* h1 = (float*)p_h1;
    float* pooled = (float*)p_pool;
    float* hidden = (float*)p_hidden;
    uint16_t* Ah = (uint16_t*)p_Ah;
    uint16_t* Al = (uint16_t*)p_Al;
    uint16_t* B1h = (uint16_t*)p_B1h;
    uint16_t* B1l = (uint16_t*)p_B1l;
    uint16_t* B2h = (uint16_t*)p_B2h;
    uint16_t* B2l = (uint16_t*)p_B2l;

    static int smem_set = 0;
    cudaFuncSetAttribute(hgemm_kernel, cudaFuncAttributeMaxDynamicSharedMemorySize,
                         2 * STAGE_BYTES);
    (void)smem_set;

    const int TB = 256;
    const dim3 ggrid((N_NODES + 127) / 128, 2);
    const int NSCAN = (N_NODES + 1023) / 1024;

    // CSR build + zero pooled sums
    zero_kernel<<<(N_GRAPHS * HID + TB - 1) / TB, TB>>>();
    hist_kernel<<<(N_EDGES + TB - 1) / TB, TB>>>(dst, batch);
    scan1_kernel<<<NSCAN, 1024>>>();
    scan2_kernel<<<1, 128>>>(NSCAN);
    scan3_kernel<<<NSCAN, 1024>>>();
    scatter_kernel<<<(N_EDGES + TB - 1) / TB, TB>>>(src, dst);

    // one-shot weight + x splits
    wsplit_kernel<<<(256 * 128 + TB - 1) / TB, TB>>>(W1l, 128, 0, B1h, B1l);
    wsplit_kernel<<<(256 * 128 + TB - 1) / TB, TB>>>(W1r, 128, 128, B1h, B1l);
    wsplit_kernel<<<(256 * 256 + TB - 1) / TB, TB>>>(W2l, 256, 0, B2h, B2l);
    wsplit_kernel<<<(256 * 256 + TB - 1) / TB, TB>>>(W2r, 256, 256, B2h, B2l);
    xsplit_kernel<<<(N_NODES * 32 + TB - 1) / TB, TB>>>(x, Ah, Al);

    // Layer 1: A panel = [split agg(x) | split x], K=256
    agg_split_kernel<IN_CH><<<(N_NODES * 32 + TB - 1) / TB, TB>>>(x, Ah, Al);
    hgemm_kernel<<<ggrid, 256, 2 * STAGE_BYTES>>>(Ah, Al, B1h, B1l, 256, b1, h1,
                                                  Ah, Al, N_NODES, nullptr, nullptr, 0);

    // Layer 2: A panel = [split agg(h1) | split h1], K=512; fused pool
    agg_split_kernel<HID><<<(N_NODES * 32 + TB - 1) / TB, TB>>>(h1, Ah, Al);
    hgemm_kernel<<<ggrid, 256, 2 * STAGE_BYTES>>>(Ah, Al, B2h, B2l, 512, b2, nullptr,
                                                  nullptr, nullptr, N_NODES, batch, pooled, 1);

    // pooled means + MLP head
    finalize_kernel<<<(N_GRAPHS * HID + TB - 1) / TB, TB>>>();
    {
        dim3 grid((N_GRAPHS + 127) / 128, HID / 128);
        gemm_bias_act<<<grid, 256>>>(pooled, HID, W3, b3, hidden, N_GRAPHS, HID, 1);
    }
    {
        dim3 grid((N_GRAPHS + 127) / 128, OUT_CH / 128);
        gemm_bias_act<<<grid, 256>>>(hidden, HID, W4, b4, out, N_GRAPHS, OUT_CH, 0);
    }
}

// round 8
// speedup vs baseline: 1.0830x; 1.0830x over previous
#include <cuda_runtime.h>
#include <cuda_bf16.h>
#include <cstdint>

#define N_NODES  100000
#define N_EDGES  1600000
#define IN_CH    128
#define HID      256
#define OUT_CH   128
#define N_GRAPHS 2048

// ---------------- scratch (device globals: no allocation allowed) ----------------
__device__ int   g_deg[N_NODES];
__device__ int   g_fill[N_NODES];
__device__ int   g_rowptr[N_NODES + 1];
__device__ int   g_col[N_EDGES];
__device__ int   g_part[128];
__device__ int   g_part2[128];
__device__ int   g_gcnt[N_GRAPHS];
__device__ uint16_t g_Ah[(size_t)N_NODES * 512];
__device__ uint16_t g_Al[(size_t)N_NODES * 512];
__device__ uint16_t g_B1h[256 * 512], g_B1l[256 * 512];
__device__ uint16_t g_B2h[256 * 512], g_B2l[256 * 512];
__device__ float g_h1 [(size_t)N_NODES * HID];
__device__ float g_pool  [N_GRAPHS * HID];
__device__ float g_hidden[N_GRAPHS * HID];

// ---------------- helpers ----------------
__device__ __forceinline__ uint16_t bf_hi_bits(float v, float& hf) {
    __nv_bfloat16 b = __float2bfloat16_rn(v);
    hf = __bfloat162float(b);
    return *(uint16_t*)&b;
}
__device__ __forceinline__ uint16_t bf_bits(float v) {
    __nv_bfloat16 b = __float2bfloat16_rn(v);
    return *(uint16_t*)&b;
}
__device__ __forceinline__ uint32_t smem_u32(const void* p) {
    uint32_t a;
    asm("{ .reg .u64 t; cvta.to.shared.u64 t, %1; cvt.u32.u64 %0, t; }" : "=r"(a) : "l"(p));
    return a;
}

// packed f32x2 helpers (head MLP GEMM)
__device__ __forceinline__ void fma2(unsigned long long& c, unsigned long long a, unsigned long long b) {
    asm("fma.rn.f32x2 %0, %1, %2, %3;" : "=l"(c) : "l"(a), "l"(b), "l"(c));
}
__device__ __forceinline__ unsigned long long pk2(float lo, float hi) {
    unsigned long long r; asm("mov.b64 %0, {%1, %2};" : "=l"(r) : "f"(lo), "f"(hi)); return r;
}
__device__ __forceinline__ unsigned long long dup2(float x) {
    unsigned long long r; asm("mov.b64 %0, {%1, %1};" : "=l"(r) : "f"(x)); return r;
}
__device__ __forceinline__ float2 upk2(unsigned long long v) {
    float2 r; asm("mov.b64 {%0, %1}, %2;" : "=f"(r.x), "=f"(r.y) : "l"(v)); return r;
}

// ---------------- CSR build + zero ----------------
__global__ void zero_kernel() {
    int i = blockIdx.x * blockDim.x + threadIdx.x;
    if (i < N_NODES) { g_deg[i] = 0; g_fill[i] = 0; }
    if (i < N_GRAPHS * HID) g_pool[i] = 0.f;
    if (i < N_GRAPHS) g_gcnt[i] = 0;
}
__global__ void hist_kernel(const int* __restrict__ dst, const int* __restrict__ batch) {
    int e = blockIdx.x * blockDim.x + threadIdx.x;
    if (e < N_EDGES) atomicAdd(&g_deg[dst[e]], 1);
    if (e < N_NODES) atomicAdd(&g_gcnt[batch[e]], 1);
}
__global__ void scan1_kernel() {
    __shared__ int sh[1024];
    int t = threadIdx.x;
    int i = blockIdx.x * 1024 + t;
    sh[t] = (i < N_NODES) ? g_deg[i] : 0;
    __syncthreads();
    for (int off = 512; off > 0; off >>= 1) {
        if (t < off) sh[t] += sh[t + off];
        __syncthreads();
    }
    if (t == 0) g_part[blockIdx.x] = sh[0];
}
__global__ void scan2_kernel(int nparts) {
    __shared__ int sh[128];
    int t = threadIdx.x;
    int v = (t < nparts) ? g_part[t] : 0;
    sh[t] = v;
    __syncthreads();
    for (int off = 1; off < 128; off <<= 1) {
        int nv = (t >= off) ? sh[t - off] : 0;
        __syncthreads();
        sh[t] += nv;
        __syncthreads();
    }
    if (t < nparts) g_part2[t] = sh[t] - v;
    if (t == 0) g_rowptr[N_NODES] = N_EDGES;
}
__global__ void scan3_kernel() {
    __shared__ int sh[1024];
    int t = threadIdx.x;
    int i = blockIdx.x * 1024 + t;
    int v = (i < N_NODES) ? g_deg[i] : 0;
    sh[t] = v;
    __syncthreads();
    for (int off = 1; off < 1024; off <<= 1) {
        int nv = (t >= off) ? sh[t - off] : 0;
        __syncthreads();
        sh[t] += nv;
        __syncthreads();
    }
    if (i < N_NODES) g_rowptr[i] = sh[t] - v + g_part2[blockIdx.x];
}
__global__ void scatter_kernel(const int* __restrict__ src, const int* __restrict__ dst) {
    int e = blockIdx.x * blockDim.x + threadIdx.x;
    if (e >= N_EDGES) return;
    int d = dst[e];
    int p = g_rowptr[d] + atomicAdd(&g_fill[d], 1);
    g_col[p] = src[e];
}

// ---------------- split writers ----------------
__device__ __forceinline__ void split_store4(uint16_t* Ah, uint16_t* Al, size_t base,
                                             float v0, float v1, float v2, float v3) {
    float hf0, hf1, hf2, hf3;
    uint16_t h0 = bf_hi_bits(v0, hf0), h1 = bf_hi_bits(v1, hf1);
    uint16_t h2 = bf_hi_bits(v2, hf2), h3 = bf_hi_bits(v3, hf3);
    uint16_t l0 = bf_bits(v0 - hf0), l1 = bf_bits(v1 - hf1);
    uint16_t l2 = bf_bits(v2 - hf2), l3 = bf_bits(v3 - hf3);
    *(uint2*)(Ah + base) = make_uint2((uint32_t)h0 | ((uint32_t)h1 << 16),
                                      (uint32_t)h2 | ((uint32_t)h3 << 16));
    *(uint2*)(Al + base) = make_uint2((uint32_t)l0 | ((uint32_t)l1 << 16),
                                      (uint32_t)l2 | ((uint32_t)l3 << 16));
}

// mean aggregation (one warp per node, 2-way edge unroll) with fused split
template <int C>
__global__ void agg_split_kernel(const float* __restrict__ feat,
                                 uint16_t* __restrict__ Ah, uint16_t* __restrict__ Al) {
    int w = (blockIdx.x * blockDim.x + threadIdx.x) >> 5;
    int lane = threadIdx.x & 31;
    if (w >= N_NODES) return;
    int beg = g_rowptr[w], end = g_rowptr[w + 1];
    constexpr int V = C / 128;
    float4 acc[V];
#pragma unroll
    for (int v = 0; v < V; v++) acc[v] = make_float4(0.f, 0.f, 0.f, 0.f);
    int j = beg;
    for (; j + 1 < end; j += 2) {
        int s0 = g_col[j], s1 = g_col[j + 1];
        const float4* r0 = (const float4*)(feat + (size_t)s0 * C);
        const float4* r1 = (const float4*)(feat + (size_t)s1 * C);
#pragma unroll
        for (int v = 0; v < V; v++) {
            float4 t0 = r0[lane + 32 * v];
            float4 t1 = r1[lane + 32 * v];
            acc[v].x += t0.x; acc[v].y += t0.y; acc[v].z += t0.z; acc[v].w += t0.w;
            acc[v].x += t1.x; acc[v].y += t1.y; acc[v].z += t1.z; acc[v].w += t1.w;
        }
    }
    if (j < end) {
        int s0 = g_col[j];
        const float4* r0 = (const float4*)(feat + (size_t)s0 * C);
#pragma unroll
        for (int v = 0; v < V; v++) {
            float4 t0 = r0[lane + 32 * v];
            acc[v].x += t0.x; acc[v].y += t0.y; acc[v].z += t0.z; acc[v].w += t0.w;
        }
    }
    float inv = (end > beg) ? 1.f / (float)(end - beg) : 0.f;
#pragma unroll
    for (int v = 0; v < V; v++) {
        size_t base = (size_t)w * 512 + (size_t)(lane + 32 * v) * 4;
        split_store4(Ah, Al, base, acc[v].x * inv, acc[v].y * inv, acc[v].z * inv, acc[v].w * inv);
    }
}

// split x (fp32 [N,128]) into A panel cols 128..255
__global__ void xsplit_kernel(const float* __restrict__ x,
                              uint16_t* __restrict__ Ah, uint16_t* __restrict__ Al) {
    int idx = blockIdx.x * blockDim.x + threadIdx.x;
    if (idx >= N_NODES * 32) return;
    int row = idx >> 5, q = idx & 31;
    float4 v = ((const float4*)x)[idx];
    split_store4(Ah, Al, (size_t)row * 512 + 128 + (size_t)q * 4, v.x, v.y, v.z, v.w);
}

// transpose + split weight W[Kw,256] into B panel
__global__ void wsplit_kernel(const float* __restrict__ W, int Kw, int cofs,
                              uint16_t* __restrict__ Bh, uint16_t* __restrict__ Bl) {
    int idx = blockIdx.x * blockDim.x + threadIdx.x;
    if (idx >= 256 * Kw) return;
    int n = idx / Kw, k = idx - n * Kw;
    float v = W[(size_t)k * 256 + n];
    float hf; uint16_t h = bf_hi_bits(v, hf);
    Bh[(size_t)n * 512 + cofs + k] = h;
    Bl[(size_t)n * 512 + cofs + k] = bf_bits(v - hf);
}

// ---------------- pre-split bf16 HMMA GEMM (R6 structure: register prefetch) ----------------
#define LDB_S 40

__device__ __forceinline__ void mma_bf16(float* c, const uint32_t* a, const uint32_t* b) {
    asm volatile(
        "mma.sync.aligned.m16n8k16.row.col.f32.bf16.bf16.f32 "
        "{%0,%1,%2,%3}, {%4,%5,%6,%7}, {%8,%9}, {%0,%1,%2,%3};"
        : "+f"(c[0]), "+f"(c[1]), "+f"(c[2]), "+f"(c[3])
        : "r"(a[0]), "r"(a[1]), "r"(a[2]), "r"(a[3]), "r"(b[0]), "r"(b[1]));
}
__device__ __forceinline__ void ldsm_x4(uint32_t* r, uint32_t addr) {
    asm volatile("ldmatrix.sync.aligned.m8n8.x4.shared.b16 {%0,%1,%2,%3}, [%4];"
                 : "=r"(r[0]), "=r"(r[1]), "=r"(r[2]), "=r"(r[3]) : "r"(addr));
}

__global__ __launch_bounds__(256, 1) void hgemm_kernel(
    const uint16_t* __restrict__ Ah, const uint16_t* __restrict__ Al,
    const uint16_t* __restrict__ Bh, const uint16_t* __restrict__ Bl,
    int K, const float* __restrict__ bias, float* __restrict__ Cc,
    uint16_t* __restrict__ oAh, uint16_t* __restrict__ oAl,
    int M, const int* __restrict__ batchp, float* __restrict__ psum, int fuse_pool)
{
    __shared__ __align__(16) uint8_t smraw[40960];
    uint16_t* As_h = (uint16_t*)(smraw);
    uint16_t* As_l = (uint16_t*)(smraw + 10240);
    uint16_t* Bs_h = (uint16_t*)(smraw + 20480);
    uint16_t* Bs_l = (uint16_t*)(smraw + 30720);

    const int tid = threadIdx.x;
    const int lane = tid & 31, wid = tid >> 5;
    const int wm = wid & 3, wn = wid >> 2;
    const int g = lane >> 2, th = lane & 3;
    const int row0 = blockIdx.x * 128;
    const int n0 = blockIdx.y * 128;

    const uint32_t sAh = smem_u32(smraw);
    const uint32_t sAl = sAh + 10240;
    const uint32_t sBh = sAh + 20480;
    const uint32_t sBl = sAh + 30720;

    const int nch = K >> 5;

    float acc[2][8][4];
#pragma unroll
    for (int mt = 0; mt < 2; mt++)
#pragma unroll
        for (int nt = 0; nt < 8; nt++)
#pragma unroll
            for (int r = 0; r < 4; r++) acc[mt][nt][r] = 0.f;

    const int lt = lane >> 3, lr = lane & 7;
    const int pr = tid >> 2, pq = tid & 3;

    uint4 ra_h[2], ra_l[2], rb_h[2], rb_l[2];

    // ---- prefetch chunk 0 ----
    {
#pragma unroll
        for (int i = 0; i < 2; i++) {
            int r = pr + i * 64;
            int ga = row0 + r;
            size_t ao = (size_t)ga * 512 + pq * 8;
            if (ga < M) { ra_h[i] = *(const uint4*)(Ah + ao); ra_l[i] = *(const uint4*)(Al + ao); }
            else        { ra_h[i] = make_uint4(0,0,0,0);      ra_l[i] = make_uint4(0,0,0,0); }
            size_t bo = (size_t)(n0 + r) * 512 + pq * 8;
            rb_h[i] = *(const uint4*)(Bh + bo);
            rb_l[i] = *(const uint4*)(Bl + bo);
        }
    }

#pragma unroll 1
    for (int c = 0; c < nch; c++) {
#pragma unroll
        for (int i = 0; i < 2; i++) {
            int r = pr + i * 64;
            int so = r * LDB_S + pq * 8;
            *(uint4*)&As_h[so] = ra_h[i];
            *(uint4*)&As_l[so] = ra_l[i];
            *(uint4*)&Bs_h[so] = rb_h[i];
            *(uint4*)&Bs_l[so] = rb_l[i];
        }
        __syncthreads();

        if (c + 1 < nch) {
            int kb = (c + 1) * 32;
#pragma unroll
            for (int i = 0; i < 2; i++) {
                int r = pr + i * 64;
                int ga = row0 + r;
                size_t ao = (size_t)ga * 512 + kb + pq * 8;
                if (ga < M) { ra_h[i] = *(const uint4*)(Ah + ao); ra_l[i] = *(const uint4*)(Al + ao); }
                else        { ra_h[i] = make_uint4(0,0,0,0);      ra_l[i] = make_uint4(0,0,0,0); }
                size_t bo = (size_t)(n0 + r) * 512 + kb + pq * 8;
                rb_h[i] = *(const uint4*)(Bh + bo);
                rb_l[i] = *(const uint4*)(Bl + bo);
            }
        }

#pragma unroll
        for (int step = 0; step < 2; step++) {
            const int k0 = step * 16;
            uint32_t aoff[2];
#pragma unroll
            for (int mt = 0; mt < 2; mt++) {
                int ar = wm * 32 + mt * 16 + (lt & 1) * 8 + lr;
                int ak = k0 + (lt >> 1) * 8;
                aoff[mt] = (uint32_t)(ar * LDB_S + ak) * 2;
            }
            uint32_t boff[4];
#pragma unroll
            for (int ntp = 0; ntp < 4; ntp++) {
                int nr = wn * 64 + ntp * 16 + (lt >> 1) * 8 + lr;
                int nk = k0 + (lt & 1) * 8;
                boff[ntp] = (uint32_t)(nr * LDB_S + nk) * 2;
            }

            uint32_t ah[2][4], al[2][4], bh[4][4], bl[4][4];
#pragma unroll
            for (int mt = 0; mt < 2; mt++) ldsm_x4(ah[mt], sAh + aoff[mt]);
#pragma unroll
            for (int ntp = 0; ntp < 4; ntp++) ldsm_x4(bh[ntp], sBh + boff[ntp]);
#pragma unroll
            for (int mt = 0; mt < 2; mt++)
#pragma unroll
                for (int nt = 0; nt < 8; nt++)
                    mma_bf16(acc[mt][nt], ah[mt], &bh[nt >> 1][(nt & 1) * 2]);

#pragma unroll
            for (int mt = 0; mt < 2; mt++) ldsm_x4(al[mt], sAl + aoff[mt]);
#pragma unroll
            for (int mt = 0; mt < 2; mt++)
#pragma unroll
                for (int nt = 0; nt < 8; nt++)
                    mma_bf16(acc[mt][nt], al[mt], &bh[nt >> 1][(nt & 1) * 2]);

#pragma unroll
            for (int ntp = 0; ntp < 4; ntp++) ldsm_x4(bl[ntp], sBl + boff[ntp]);
#pragma unroll
            for (int mt = 0; mt < 2; mt++)
#pragma unroll
                for (int nt = 0; nt < 8; nt++)
                    mma_bf16(acc[mt][nt], ah[mt], &bl[nt >> 1][(nt & 1) * 2]);
        }
        __syncthreads();
    }

    if (!fuse_pool) {
#pragma unroll
        for (int mt = 0; mt < 2; mt++) {
            int rbase = row0 + wm * 32 + mt * 16 + g;
#pragma unroll
            for (int nt = 0; nt < 8; nt++) {
                int col = n0 + wn * 64 + nt * 8 + th * 2;
                float bx = bias[col], by = bias[col + 1];
                float2 v0 = make_float2(fmaxf(acc[mt][nt][0] + bx, 0.f),
                                        fmaxf(acc[mt][nt][1] + by, 0.f));
                float2 v1 = make_float2(fmaxf(acc[mt][nt][2] + bx, 0.f),
                                        fmaxf(acc[mt][nt][3] + by, 0.f));
                if (rbase < M) {
                    *(float2*)(Cc + (size_t)rbase * 256 + col) = v0;
                    float hf0, hf1;
                    uint16_t h0 = bf_hi_bits(v0.x, hf0), h1 = bf_hi_bits(v0.y, hf1);
                    uint16_t l0 = bf_bits(v0.x - hf0),   l1 = bf_bits(v0.y - hf1);
                    size_t ob = (size_t)rbase * 512 + 256 + col;
                    *(uint32_t*)(oAh + ob) = (uint32_t)h0 | ((uint32_t)h1 << 16);
                    *(uint32_t*)(oAl + ob) = (uint32_t)l0 | ((uint32_t)l1 << 16);
                }
                if (rbase + 8 < M) {
                    *(float2*)(Cc + (size_t)(rbase + 8) * 256 + col) = v1;
                    float hf0, hf1;
                    uint16_t h0 = bf_hi_bits(v1.x, hf0), h1 = bf_hi_bits(v1.y, hf1);
                    uint16_t l0 = bf_bits(v1.x - hf0),   l1 = bf_bits(v1.y - hf1);
                    size_t ob = (size_t)(rbase + 8) * 512 + 256 + col;
                    *(uint32_t*)(oAh + ob) = (uint32_t)h0 | ((uint32_t)h1 << 16);
                    *(uint32_t*)(oAl + ob) = (uint32_t)l0 | ((uint32_t)l1 << 16);
                }
            }
        }
    } else {
        float* red = (float*)smraw;              // [128][66]
        int*   sbat = (int*)(smraw + 33792);     // [128]
#pragma unroll 1
        for (int h = 0; h < 2; h++) {
            __syncthreads();
            if (tid < 128) sbat[tid] = (row0 + tid < M) ? batchp[row0 + tid] : -1;
            if (wn == h) {
#pragma unroll
                for (int mt = 0; mt < 2; mt++) {
                    int rl = wm * 32 + mt * 16 + g;
#pragma unroll
                    for (int nt = 0; nt < 8; nt++) {
                        int cl = nt * 8 + th * 2;
                        int colg = n0 + h * 64 + cl;
                        float bx = bias[colg], by = bias[colg + 1];
                        red[rl * 66 + cl]       = fmaxf(acc[mt][nt][0] + bx, 0.f);
                        red[rl * 66 + cl + 1]   = fmaxf(acc[mt][nt][1] + by, 0.f);
                        red[(rl + 8) * 66 + cl]     = fmaxf(acc[mt][nt][2] + bx, 0.f);
                        red[(rl + 8) * 66 + cl + 1] = fmaxf(acc[mt][nt][3] + by, 0.f);
                    }
                }
            }
            __syncthreads();
            int cl = tid & 63, rh = tid >> 6;
            float run = 0.f; int cur = -1;
#pragma unroll 1
            for (int r = rh * 32; r < rh * 32 + 32; r++) {
                int gb = sbat[r];
                if (gb != cur) {
                    if (cur >= 0)
                        atomicAdd(&psum[(size_t)cur * 256 + n0 + h * 64 + cl], run);
                    run = 0.f; cur = gb;
                }
                if (gb >= 0) run += red[r * 66 + cl];
            }
            if (cur >= 0)
                atomicAdd(&psum[(size_t)cur * 256 + n0 + h * 64 + cl], run);
        }
    }
}

// ---------------- finalize pooled means ----------------
__global__ void finalize_kernel() {
    int i = blockIdx.x * blockDim.x + threadIdx.x;
    if (i >= N_GRAPHS * HID) return;
    float c = (float)g_gcnt[i >> 8];
    g_pool[i] = g_pool[i] / fmaxf(c, 1.f);
}

// ---------------- fp32 GEMM (head MLP only; small) ----------------
__global__ __launch_bounds__(256, 2) void gemm_bias_act(
    const float* __restrict__ A1, int K1, const float* __restrict__ B1,
    const float* __restrict__ bias, float* __restrict__ Cc,
    int M, int Nout, int do_relu)
{
    __shared__ float As[8][132];
    __shared__ float Bs[8][128];
    int tid = threadIdx.x;
    int tx = tid & 15, ty = tid >> 4;
    int row0 = blockIdx.x * 128;
    int col0 = blockIdx.y * 128;

    unsigned long long acc[8][4];
#pragma unroll
    for (int i = 0; i < 8; i++)
#pragma unroll
        for (int j = 0; j < 4; j++) acc[i][j] = 0ull;

    int lm = tid >> 1, lk = (tid & 1) * 4;
    int bk = tid >> 5, bn = (tid & 31) * 4;

#pragma unroll 1
    for (int k0 = 0; k0 < K1; k0 += 8) {
        float4 av = make_float4(0.f, 0.f, 0.f, 0.f);
        int r = row0 + lm;
        if (r < M) av = *(const float4*)(A1 + (size_t)r * K1 + k0 + lk);
        float4 bv = *(const float4*)(B1 + (size_t)(k0 + bk) * Nout + col0 + bn);
        __syncthreads();
        As[lk + 0][lm] = av.x; As[lk + 1][lm] = av.y;
        As[lk + 2][lm] = av.z; As[lk + 3][lm] = av.w;
        *(float4*)&Bs[bk][bn] = bv;
        __syncthreads();
#pragma unroll
        for (int k = 0; k < 8; k++) {
            float4 a0 = *(const float4*)&As[k][ty * 4];
            float4 a1 = *(const float4*)&As[k][64 + ty * 4];
            float4 b0 = *(const float4*)&Bs[k][tx * 4];
            float4 b1 = *(const float4*)&Bs[k][64 + tx * 4];
            unsigned long long bp[4];
            bp[0] = pk2(b0.x, b0.y); bp[1] = pk2(b0.z, b0.w);
            bp[2] = pk2(b1.x, b1.y); bp[3] = pk2(b1.z, b1.w);
            float a[8] = {a0.x, a0.y, a0.z, a0.w, a1.x, a1.y, a1.z, a1.w};
#pragma unroll
            for (int i = 0; i < 8; i++) {
                unsigned long long ai = dup2(a[i]);
                fma2(acc[i][0], ai, bp[0]);
                fma2(acc[i][1], ai, bp[1]);
                fma2(acc[i][2], ai, bp[2]);
                fma2(acc[i][3], ai, bp[3]);
            }
        }
    }
#pragma unroll
    for (int i = 0; i < 8; i++) {
        int r = row0 + ((i < 4) ? ty * 4 + i : 64 + ty * 4 + (i - 4));
        if (r >= M) continue;
#pragma unroll
        for (int j = 0; j < 4; j++) {
            int c = col0 + ((j < 2) ? tx * 4 + j * 2 : 64 + tx * 4 + (j - 2) * 2);
            float2 v = upk2(acc[i][j]);
            v.x += bias[c]; v.y += bias[c + 1];
            if (do_relu) { v.x = fmaxf(v.x, 0.f); v.y = fmaxf(v.y, 0.f); }
            *(float2*)(Cc + (size_t)r * Nout + c) = v;
        }
    }
}

// ---------------- launch ----------------
extern "C" void kernel_launch(void* const* d_in, const int* in_sizes, int n_in,
                              void* d_out, int out_size) {
    const float* x   = (const float*)d_in[0];
    const int*   ei  = (const int*)d_in[1];
    const int*   src = ei;
    const int*   dst = ei + N_EDGES;
    const int* batch = (const int*)d_in[2];
    const float* W1l = (const float*)d_in[3];
    const float* b1  = (const float*)d_in[4];
    const float* W1r = (const float*)d_in[5];
    const float* W2l = (const float*)d_in[6];
    const float* b2  = (const float*)d_in[7];
    const float* W2r = (const float*)d_in[8];
    const float* W3  = (const float*)d_in[9];
    const float* b3  = (const float*)d_in[10];
    const float* W4  = (const float*)d_in[11];
    const float* b4  = (const float*)d_in[12];
    float* out = (float*)d_out;

    void *p_h1, *p_pool, *p_hidden, *p_Ah, *p_Al, *p_B1h, *p_B1l, *p_B2h, *p_B2l;
    cudaGetSymbolAddress(&p_h1, g_h1);
    cudaGetSymbolAddress(&p_pool, g_pool);
    cudaGetSymbolAddress(&p_hidden, g_hidden);
    cudaGetSymbolAddress(&p_Ah, g_Ah);
    cudaGetSymbolAddress(&p_Al, g_Al);
    cudaGetSymbolAddress(&p_B1h, g_B1h);
    cudaGetSymbolAddress(&p_B1l, g_B1l);
    cudaGetSymbolAddress(&p_B2h, g_B2h);
    cudaGetSymbolAddress(&p_B2l, g_B2l);
    float* h1 = (float*)p_h1;
    float* pooled = (float*)p_pool;
    float* hidden = (float*)p_hidden;
    uint16_t* Ah = (uint16_t*)p_Ah;
    uint16_t* Al = (uint16_t*)p_Al;
    uint16_t* B1h = (uint16_t*)p_B1h;
    uint16_t* B1l = (uint16_t*)p_B1l;
    uint16_t* B2h = (uint16_t*)p_B2h;
    uint16_t* B2l = (uint16_t*)p_B2l;

    // fork-join stream for independent split chain (created once; host-side only)
    static cudaStream_t s_aux = nullptr;
    static cudaEvent_t ev_fork = nullptr, ev_join = nullptr;
    if (!s_aux) {
        cudaStreamCreateWithFlags(&s_aux, cudaStreamNonBlocking);
        cudaEventCreateWithFlags(&ev_fork, cudaEventDisableTiming);
        cudaEventCreateWithFlags(&ev_join, cudaEventDisableTiming);
    }

    const int TB = 256;
    const dim3 ggrid((N_NODES + 127) / 128, 2);
    const int NSCAN = (N_NODES + 1023) / 1024;

    // ---- fork: weight/x splits on aux stream ----
    cudaEventRecord(ev_fork, 0);
    cudaStreamWaitEvent(s_aux, ev_fork, 0);
    wsplit_kernel<<<(256 * 128 + TB - 1) / TB, TB, 0, s_aux>>>(W1l, 128, 0, B1h, B1l);
    wsplit_kernel<<<(256 * 128 + TB - 1) / TB, TB, 0, s_aux>>>(W1r, 128, 128, B1h, B1l);
    wsplit_kernel<<<(256 * 256 + TB - 1) / TB, TB, 0, s_aux>>>(W2l, 256, 0, B2h, B2l);
    wsplit_kernel<<<(256 * 256 + TB - 1) / TB, TB, 0, s_aux>>>(W2r, 256, 256, B2h, B2l);
    xsplit_kernel<<<(N_NODES * 32 + TB - 1) / TB, TB, 0, s_aux>>>(x, Ah, Al);
    cudaEventRecord(ev_join, s_aux);

    // ---- main stream: CSR build + zero pooled sums ----
    zero_kernel<<<(N_GRAPHS * HID + TB - 1) / TB, TB>>>();
    hist_kernel<<<(N_EDGES + TB - 1) / TB, TB>>>(dst, batch);
    scan1_kernel<<<NSCAN, 1024>>>();
    scan2_kernel<<<1, 128>>>(NSCAN);
    scan3_kernel<<<NSCAN, 1024>>>();
    scatter_kernel<<<(N_EDGES + TB - 1) / TB, TB>>>(src, dst);

    // Layer 1 aggregation (needs CSR + x only)
    agg_split_kernel<IN_CH><<<(N_NODES * 32 + TB - 1) / TB, TB>>>(x, Ah, Al);

    // join before gemm1 (needs xsplit + weight splits)
    cudaStreamWaitEvent(0, ev_join, 0);
    hgemm_kernel<<<ggrid, 256>>>(Ah, Al, B1h, B1l, 256, b1, h1, Ah, Al, N_NODES,
                                 nullptr, nullptr, 0);

    // Layer 2: A panel = [split agg(h1) | split h1], K=512; fused pool
    agg_split_kernel<HID><<<(N_NODES * 32 + TB - 1) / TB, TB>>>(h1, Ah, Al);
    hgemm_kernel<<<ggrid, 256>>>(Ah, Al, B2h, B2l, 512, b2, nullptr, nullptr, nullptr,
                                 N_NODES, batch, pooled, 1);

    // pooled means + MLP head
    finalize_kernel<<<(N_GRAPHS * HID + TB - 1) / TB, TB>>>();
    {
        dim3 grid((N_GRAPHS + 127) / 128, HID / 128);
        gemm_bias_act<<<grid, 256>>>(pooled, HID, W3, b3, hidden, N_GRAPHS, HID, 1);
    }
    {
        dim3 grid((N_GRAPHS + 127) / 128, OUT_CH / 128);
        gemm_bias_act<<<grid, 256>>>(hidden, HID, W4, b4, out, N_GRAPHS, OUT_CH, 0);
    }
}